// round 3
// baseline (speedup 1.0000x reference)
#include <cuda_runtime.h>
#include <math.h>

// Problem constants
#define SEQ   256
#define BSZ   16
#define HID   512
#define EMB   768
#define VOC   30522
#define TM1   99

// ---------------- scratch (device globals; no allocations) ----------------
__device__ float g_gi_f[SEQ*BSZ*1536];     // encoder fwd gi
__device__ float g_gi_b[SEQ*BSZ*1536];     // encoder bwd gi
__device__ float g_enc_out[BSZ*SEQ*1024];  // [b][s][1024] concat(fwd,bwd)
__device__ float g_hf[HID*BSZ];            // h stored [k*16+b]
__device__ float g_hb[HID*BSZ];
__device__ float g_hd[HID*BSZ];
__device__ float g_v[1024];                // folded attention vector (enc part)
__device__ float g_c0;                     // folded attention scalar
__device__ float g_ctx2h[BSZ*1024];
__device__ float g_ctx[BSZ*HID];
__device__ float g_ctxgi[BSZ*1536];        // ctx@dec_Wih[:,768:].T + dec_bih
__device__ float g_gid[TM1*BSZ*1536];      // decoder gi
__device__ float g_Hs[TM1*BSZ*HID];        // decoder hidden states [ (t*16+b) * 512 + i ]
__device__ float g_base[BSZ*VOC];          // ctx@out_W[:,512:].T + out_b
__device__ unsigned int g_bar_count[4];
__device__ unsigned int g_bar_gen[4];

// ---------------- software grid barrier (all blocks resident) --------------
__device__ __forceinline__ void grid_barrier(int id, unsigned nb, unsigned &gen) {
    __syncthreads();
    if (threadIdx.x == 0) {
        __threadfence();
        unsigned t = atomicAdd(&g_bar_count[id], 1u);
        if (t == nb - 1u) {
            atomicExch(&g_bar_count[id], 0u);
            __threadfence();
            atomicAdd(&g_bar_gen[id], 1u);
        } else {
            while (atomicAdd(&g_bar_gen[id], 0u) == gen) { __nanosleep(64); }
        }
    }
    gen++;
    __syncthreads();
    __threadfence();
}

__device__ __forceinline__ float sigmoidf_(float x) { return 1.0f / (1.0f + expf(-x)); }

// ---------------- fold attention: v[k] = comb_W @ attn_W[:, k], c0 ---------
__global__ void fold_kernel(const float* __restrict__ attn_W, const float* __restrict__ attn_b,
                            const float* __restrict__ comb_W, const float* __restrict__ comb_b) {
    int k = blockIdx.x * 256 + threadIdx.x;
    if (k < 1024) {
        float acc = 0.f;
        for (int j = 0; j < 512; j++) acc += comb_W[j] * attn_W[(size_t)j * 1536 + k];
        g_v[k] = acc;
    }
    if (blockIdx.x == 0 && threadIdx.x == 0) {
        float c = comb_b[0];
        for (int j = 0; j < 512; j++) c += comb_W[j] * attn_b[j];
        g_c0 = c;
    }
}

// ---------------- generic 128x128x8 SGEMM: C = A @ W.T (+epilogue) ----------
// MODE 0: A rows from bert_output, C -> g_gi_f / g_gi_b (sel), + bias[n]
// MODE 1: A rows gathered from emb via token ids, C -> g_gid, + g_ctxgi[b][n]
// MODE 2: A = g_Hs, C -> out[(b*99+t)*VOC + n], + g_base[b][n]
template<int MODE>
__global__ void __launch_bounds__(256) sgemm(
    const float* __restrict__ Asrc, const float* __restrict__ W, int ldw,
    const float* __restrict__ bias, const int* __restrict__ toks,
    float* __restrict__ Cout, int sel, int M, int N, int K)
{
    const int BM = 128, BN = 128, BK = 8;
    __shared__ float As[BK][BM];
    __shared__ float Bs[BK][BN];

    int tid = threadIdx.x;
    int bn = blockIdx.x, bm = blockIdx.y;
    int row0 = bm * BM, col0 = bn * BN;
    int tx = tid & 15, ty = tid >> 4;

    // A load mapping
    int a_m = tid >> 1;
    int a_k = (tid & 1) * 4;
    int am = row0 + a_m;
    bool mvalid = (am < M);
    const float* Ap = nullptr;
    if (mvalid) {
        if (MODE == 0) {
            int s = am >> 4, b = am & 15;
            Ap = Asrc + ((size_t)b * SEQ + s) * EMB;
        } else if (MODE == 1) {
            int t = am >> 4, b = am & 15;
            int tok = toks[b * 100 + t];
            Ap = Asrc + (size_t)tok * EMB;
        } else {
            Ap = g_Hs + (size_t)am * HID;
        }
    }
    // W load mapping
    int b_n = tid >> 1;
    int b_k = (tid & 1) * 4;
    int wn = col0 + b_n;
    bool nvalid = (wn < N);
    const float* Wp = nvalid ? (W + (size_t)wn * ldw) : nullptr;

    float acc[8][8];
    #pragma unroll
    for (int i = 0; i < 8; i++)
        #pragma unroll
        for (int j = 0; j < 8; j++) acc[i][j] = 0.f;

    for (int k0 = 0; k0 < K; k0 += BK) {
        float4 av = make_float4(0.f, 0.f, 0.f, 0.f);
        if (mvalid) av = *reinterpret_cast<const float4*>(Ap + k0 + a_k);
        As[a_k + 0][a_m] = av.x;
        As[a_k + 1][a_m] = av.y;
        As[a_k + 2][a_m] = av.z;
        As[a_k + 3][a_m] = av.w;

        float4 wv = make_float4(0.f, 0.f, 0.f, 0.f);
        if (nvalid) wv = *reinterpret_cast<const float4*>(Wp + k0 + b_k);
        Bs[b_k + 0][b_n] = wv.x;
        Bs[b_k + 1][b_n] = wv.y;
        Bs[b_k + 2][b_n] = wv.z;
        Bs[b_k + 3][b_n] = wv.w;
        __syncthreads();

        #pragma unroll
        for (int kk = 0; kk < BK; kk++) {
            float4 a0 = *reinterpret_cast<const float4*>(&As[kk][ty * 8]);
            float4 a1 = *reinterpret_cast<const float4*>(&As[kk][ty * 8 + 4]);
            float4 b0 = *reinterpret_cast<const float4*>(&Bs[kk][tx * 8]);
            float4 b1 = *reinterpret_cast<const float4*>(&Bs[kk][tx * 8 + 4]);
            float ar[8] = {a0.x, a0.y, a0.z, a0.w, a1.x, a1.y, a1.z, a1.w};
            float br[8] = {b0.x, b0.y, b0.z, b0.w, b1.x, b1.y, b1.z, b1.w};
            #pragma unroll
            for (int i = 0; i < 8; i++)
                #pragma unroll
                for (int j = 0; j < 8; j++) acc[i][j] += ar[i] * br[j];
        }
        __syncthreads();
    }

    #pragma unroll
    for (int i = 0; i < 8; i++) {
        int m = row0 + ty * 8 + i;
        if (m >= M) break;
        int b = m & 15, t = m >> 4;
        #pragma unroll
        for (int j = 0; j < 8; j++) {
            int n = col0 + tx * 8 + j;
            if (n >= N) continue;
            float val = acc[i][j];
            if (MODE == 0) {
                val += bias[n];
                float* dst = sel ? g_gi_b : g_gi_f;
                dst[(size_t)m * 1536 + n] = val;
            } else if (MODE == 1) {
                val += g_ctxgi[b * 1536 + n];
                g_gid[(size_t)m * 1536 + n] = val;
            } else {
                val += g_base[(size_t)b * VOC + n];
                Cout[((size_t)b * TM1 + t) * VOC + n] = val;
            }
        }
    }
}

// ---------------- encoder scan: both directions, persistent ----------------
__global__ void __launch_bounds__(256) enc_scan(
    const float* __restrict__ Whh_f, const float* __restrict__ bhh_f,
    const float* __restrict__ Whh_b, const float* __restrict__ bhh_b)
{
    int dir = blockIdx.x >> 5;   // 0 = fwd, 1 = bwd; 32 blocks each
    int blk = blockIdx.x & 31;
    int tid = threadIdx.x;
    int b = tid & 15;
    int i = blk * 16 + (tid >> 4);

    const float* Whh = dir ? Whh_b : Whh_f;
    const float* bhh = dir ? bhh_b : bhh_f;
    const float* gi  = dir ? g_gi_b : g_gi_f;
    float* hg = dir ? g_hb : g_hf;

    __shared__ float hs[HID * 16];  // [k][b], 32KB
    for (int x = tid; x < HID * 16; x += 256) hs[x] = 0.f;
    __syncthreads();

    unsigned gen = g_bar_gen[dir];
    const float bh_r = bhh[i], bh_z = bhh[i + 512], bh_n = bhh[i + 1024];
    const float* Wr = Whh + (size_t)i * HID;
    const float* Wz = Whh + (size_t)(i + 512) * HID;
    const float* Wn = Whh + (size_t)(i + 1024) * HID;

    for (int step = 0; step < SEQ; step++) {
        int s = dir ? (SEQ - 1 - step) : step;
        float ar = bh_r, az = bh_z, an = bh_n;
        #pragma unroll 4
        for (int k = 0; k < HID; k += 4) {
            float4 wr = *reinterpret_cast<const float4*>(Wr + k);
            float4 wz = *reinterpret_cast<const float4*>(Wz + k);
            float4 wn = *reinterpret_cast<const float4*>(Wn + k);
            float h0 = hs[(k + 0) * 16 + b];
            float h1 = hs[(k + 1) * 16 + b];
            float h2 = hs[(k + 2) * 16 + b];
            float h3 = hs[(k + 3) * 16 + b];
            ar += wr.x * h0 + wr.y * h1 + wr.z * h2 + wr.w * h3;
            az += wz.x * h0 + wz.y * h1 + wz.z * h2 + wz.w * h3;
            an += wn.x * h0 + wn.y * h1 + wn.z * h2 + wn.w * h3;
        }
        const float* gp = gi + ((size_t)s * 16 + b) * 1536 + i;
        float r = sigmoidf_(gp[0] + ar);
        float z = sigmoidf_(gp[512] + az);
        float n = tanhf(gp[1024] + r * an);
        float hprev = hs[i * 16 + b];
        float hnew = (1.f - z) * n + z * hprev;
        hg[i * 16 + b] = hnew;
        g_enc_out[((size_t)b * SEQ + s) * 1024 + dir * 512 + i] = hnew;

        grid_barrier(dir, 32, gen);
        for (int x = tid; x < HID * 16; x += 256) hs[x] = hg[x];
        __syncthreads();
    }
}

// ---------------- attention: scores + softmax + ctx2h (once) ---------------
__global__ void attn_kernel(const int* __restrict__ amask) {
    int b = blockIdx.x, tid = threadIdx.x;
    __shared__ float vs[1024];
    __shared__ float ws[SEQ];
    __shared__ float red[16];
    for (int x = tid; x < 1024; x += 256) vs[x] = g_v[x];
    __syncthreads();

    const float* row = g_enc_out + ((size_t)b * SEQ + tid) * 1024;
    float acc = 0.f;
    for (int k = 0; k < 1024; k += 4) {
        float4 e = *reinterpret_cast<const float4*>(row + k);
        acc += e.x * vs[k] + e.y * vs[k + 1] + e.z * vs[k + 2] + e.w * vs[k + 3];
    }
    float sc = acc + g_c0;
    if (amask[b * SEQ + tid] == 0) sc = -1e9f;

    // block max
    float m = sc;
    #pragma unroll
    for (int o = 16; o; o >>= 1) m = fmaxf(m, __shfl_xor_sync(0xffffffffu, m, o));
    if ((tid & 31) == 0) red[tid >> 5] = m;
    __syncthreads();
    if (tid < 32) {
        float t = (tid < 8) ? red[tid] : -3.4e38f;
        #pragma unroll
        for (int o = 4; o; o >>= 1) t = fmaxf(t, __shfl_xor_sync(0xffffffffu, t, o));
        if (tid == 0) red[0] = t;
    }
    __syncthreads();
    float mx = red[0];
    float e = expf(sc - mx);
    // block sum
    float sm = e;
    #pragma unroll
    for (int o = 16; o; o >>= 1) sm += __shfl_xor_sync(0xffffffffu, sm, o);
    __syncthreads();
    if ((tid & 31) == 0) red[8 + (tid >> 5)] = sm;
    __syncthreads();
    if (tid < 32) {
        float t = (tid < 8) ? red[8 + tid] : 0.f;
        #pragma unroll
        for (int o = 4; o; o >>= 1) t += __shfl_xor_sync(0xffffffffu, t, o);
        if (tid == 0) red[0] = t;
    }
    __syncthreads();
    float total = red[0];
    ws[tid] = e / total;
    __syncthreads();

    #pragma unroll
    for (int kk = 0; kk < 4; kk++) {
        int k = tid + kk * 256;
        float a2 = 0.f;
        for (int s = 0; s < SEQ; s++)
            a2 += ws[s] * g_enc_out[((size_t)b * SEQ + s) * 1024 + k];
        g_ctx2h[b * 1024 + k] = a2;
    }
}

// ---------------- small GEMMs: proj / ctx_gi / base ------------------------
// mode 0: g_ctx   = g_ctx2h @ proj_W.T + proj_b        (N=512,  K=1024, ldw=1024, koff=0)
// mode 1: g_ctxgi = g_ctx @ dec_Wih[:,768:].T + dec_bih (N=1536, K=512, ldw=1280, koff=768)
// mode 2: g_base  = g_ctx @ out_W[:,512:].T + out_b     (N=VOC,  K=512, ldw=1024, koff=512)
__global__ void small_mm(const float* __restrict__ W, const float* __restrict__ bias,
                         int mode, int N, int K, int ldw, int koff) {
    int idx = blockIdx.x * 256 + threadIdx.x;
    if (idx >= 16 * N) return;
    int b = idx & 15, n = idx >> 4;
    const float* A = (mode == 0) ? (g_ctx2h + b * 1024) : (g_ctx + b * 512);
    const float* w = W + (size_t)n * ldw + koff;
    float acc = bias[n];
    for (int k = 0; k < K; k += 4) {
        float4 wv = *reinterpret_cast<const float4*>(w + k);
        acc += A[k] * wv.x + A[k + 1] * wv.y + A[k + 2] * wv.z + A[k + 3] * wv.w;
    }
    if (mode == 0)      g_ctx[b * 512 + n] = acc;
    else if (mode == 1) g_ctxgi[b * 1536 + n] = acc;
    else                g_base[(size_t)b * VOC + n] = acc;
}

// ---------------- decoder scan: persistent -------------------------------
__global__ void __launch_bounds__(256) dec_scan(const float* __restrict__ Whh,
                                                const float* __restrict__ bhh) {
    int blk = blockIdx.x;
    int tid = threadIdx.x;
    int b = tid & 15;
    int i = blk * 16 + (tid >> 4);

    __shared__ float hs[HID * 16];
    for (int x = tid; x < HID * 16; x += 256) {
        float hv = g_hf[x] + g_hb[x];
        hs[x] = hv;
        g_hd[x] = hv;
    }
    __syncthreads();

    unsigned gen = g_bar_gen[2];
    const float bh_r = bhh[i], bh_z = bhh[i + 512], bh_n = bhh[i + 1024];
    const float* Wr = Whh + (size_t)i * HID;
    const float* Wz = Whh + (size_t)(i + 512) * HID;
    const float* Wn = Whh + (size_t)(i + 1024) * HID;

    for (int t = 0; t < TM1; t++) {
        float ar = bh_r, az = bh_z, an = bh_n;
        #pragma unroll 4
        for (int k = 0; k < HID; k += 4) {
            float4 wr = *reinterpret_cast<const float4*>(Wr + k);
            float4 wz = *reinterpret_cast<const float4*>(Wz + k);
            float4 wn = *reinterpret_cast<const float4*>(Wn + k);
            float h0 = hs[(k + 0) * 16 + b];
            float h1 = hs[(k + 1) * 16 + b];
            float h2 = hs[(k + 2) * 16 + b];
            float h3 = hs[(k + 3) * 16 + b];
            ar += wr.x * h0 + wr.y * h1 + wr.z * h2 + wr.w * h3;
            az += wz.x * h0 + wz.y * h1 + wz.z * h2 + wz.w * h3;
            an += wn.x * h0 + wn.y * h1 + wn.z * h2 + wn.w * h3;
        }
        const float* gp = g_gid + ((size_t)t * 16 + b) * 1536 + i;
        float r = sigmoidf_(gp[0] + ar);
        float z = sigmoidf_(gp[512] + az);
        float n = tanhf(gp[1024] + r * an);
        float hprev = hs[i * 16 + b];
        float hnew = (1.f - z) * n + z * hprev;
        g_hd[i * 16 + b] = hnew;
        g_Hs[((size_t)t * 16 + b) * HID + i] = hnew;

        grid_barrier(2, 32, gen);
        for (int x = tid; x < HID * 16; x += 256) hs[x] = g_hd[x];
        __syncthreads();
    }
}

// ---------------- launch -------------------------------------------------
extern "C" void kernel_launch(void* const* d_in, const int* in_sizes, int n_in,
                              void* d_out, int out_size) {
    const float* bert   = (const float*)d_in[0];
    const int*   amask  = (const int*)d_in[1];
    const int*   ids    = (const int*)d_in[2];
    const float* emb    = (const float*)d_in[3];
    const float* eWih_f = (const float*)d_in[4];
    const float* eWhh_f = (const float*)d_in[5];
    const float* ebih_f = (const float*)d_in[6];
    const float* ebhh_f = (const float*)d_in[7];
    const float* eWih_b = (const float*)d_in[8];
    const float* eWhh_b = (const float*)d_in[9];
    const float* ebih_b = (const float*)d_in[10];
    const float* ebhh_b = (const float*)d_in[11];
    const float* dWih   = (const float*)d_in[12];
    const float* dWhh   = (const float*)d_in[13];
    const float* dbih   = (const float*)d_in[14];
    const float* dbhh   = (const float*)d_in[15];
    const float* attn_W = (const float*)d_in[16];
    const float* attn_b = (const float*)d_in[17];
    const float* comb_W = (const float*)d_in[18];
    const float* comb_b = (const float*)d_in[19];
    const float* proj_W = (const float*)d_in[20];
    const float* proj_b = (const float*)d_in[21];
    const float* out_W  = (const float*)d_in[22];
    const float* out_b  = (const float*)d_in[23];
    float* out = (float*)d_out;

    // attention folding (tiny)
    fold_kernel<<<4, 256>>>(attn_W, attn_b, comb_W, comb_b);

    // encoder input gates (big GEMMs)
    sgemm<0><<<dim3(12, 32), 256>>>(bert, eWih_f, 768, ebih_f, nullptr, nullptr, 0, 4096, 1536, 768);
    sgemm<0><<<dim3(12, 32), 256>>>(bert, eWih_b, 768, ebih_b, nullptr, nullptr, 1, 4096, 1536, 768);

    // bidirectional encoder scan (persistent, both dirs concurrent)
    enc_scan<<<64, 256>>>(eWhh_f, ebhh_f, eWhh_b, ebhh_b);

    // attention (once — h-dependence cancels in softmax)
    attn_kernel<<<16, 256>>>(amask);

    // ctx = ctx2h @ proj_W.T + proj_b
    small_mm<<<32, 256>>>(proj_W, proj_b, 0, 512, 1024, 1024, 0);
    // ctx_gi = ctx @ dec_Wih[:,768:].T + dec_bih
    small_mm<<<96, 256>>>(dWih, dbih, 1, 1536, 512, 1280, 768);

    // decoder input gates: gathered emb rows GEMM + ctx_gi
    sgemm<1><<<dim3(12, 13), 256>>>(emb, dWih, 1280, nullptr, ids, nullptr, 0, 1584, 1536, 768);

    // decoder scan (persistent)
    dec_scan<<<32, 256>>>(dWhh, dbhh);

    // base = ctx @ out_W[:,512:].T + out_b
    small_mm<<<1908, 256>>>(out_W, out_b, 2, VOC, 512, 1024, 512);

    // logits = Hs @ out_W[:,:512].T + base  ->  out[b][t][v]
    sgemm<2><<<dim3(239, 13), 256>>>(nullptr, out_W, 1024, nullptr, nullptr, out, 0, 1584, VOC, 512);
}